// round 15
// baseline (speedup 1.0000x reference)
#include <cuda_runtime.h>
#include <cuda_fp16.h>
#include <math.h>
#include <stdint.h>

// ---------------- scratch (device globals: no allocation allowed) ----------
__device__ float g_q[2048 * 4096];
__device__ float g_k[2048 * 1024];
__device__ float g_cos[2048 * 64];
__device__ float g_sin[2048 * 64];
__device__ __half g_wqt[4096 * 4096];   // Wq^T [N][K]
__device__ __half g_wkt[1024 * 4096];
__device__ __half g_wvt[1024 * 4096];
__device__ __half g_wot[4096 * 4096];   // Wo^T
__device__ __half g_hh[2048 * 4096];    // hidden hi
__device__ __half g_hl[2048 * 4096];    // hidden lo
__device__ __half g_oh[2048 * 4096];    // attn out hi
__device__ __half g_ol[2048 * 4096];    // attn out lo
__device__ __half g_kh[2048 * 1024];    // K after rmsnorm+rope, fp16
__device__ __half g_vt[1024 * 2048];    // V transposed [ch][tok] fp16

// ==================== shared helpers =======================================
__device__ __forceinline__ void mma16816(float acc[4], const uint32_t a[4],
                                         const uint32_t b[2]) {
    asm("mma.sync.aligned.m16n8k16.row.col.f32.f16.f16.f32 "
        "{%0,%1,%2,%3}, {%4,%5,%6,%7}, {%8,%9}, {%0,%1,%2,%3};\n"
        : "+f"(acc[0]), "+f"(acc[1]), "+f"(acc[2]), "+f"(acc[3])
        : "r"(a[0]), "r"(a[1]), "r"(a[2]), "r"(a[3]), "r"(b[0]), "r"(b[1]));
}

__device__ __forceinline__ void ldsm_x4(uint32_t& r0, uint32_t& r1,
                                        uint32_t& r2, uint32_t& r3,
                                        uint32_t addr) {
    asm volatile(
        "ldmatrix.sync.aligned.m8n8.x4.shared.b16 {%0,%1,%2,%3}, [%4];"
        : "=r"(r0), "=r"(r1), "=r"(r2), "=r"(r3) : "r"(addr));
}

__device__ __forceinline__ uint32_t smem_u32(const void* p) {
    uint32_t a;
    asm("{ .reg .u64 t; cvta.to.shared.u64 t, %1; cvt.u32.u64 %0, t; }"
        : "=r"(a) : "l"(p));
    return a;
}

__device__ __forceinline__ void cp16(uint32_t smem, const void* g) {
    asm volatile("cp.async.cg.shared.global [%0], [%1], 16;\n"
                 :: "r"(smem), "l"(g) : "memory");
}
#define CP_COMMIT asm volatile("cp.async.commit_group;\n" ::: "memory")
#define CP_WAIT1 asm volatile("cp.async.wait_group 1;\n" ::: "memory")
#define CP_WAIT0 asm volatile("cp.async.wait_group 0;\n" ::: "memory")

// fp16 exact split: x = hi + lo (~24 bits)
__device__ __forceinline__ void splitA2(float x, float y, uint32_t& hi, uint32_t& lo) {
    __half hx = __float2half_rn(x);
    __half hy = __float2half_rn(y);
    __half lx = __float2half_rn(x - __half2float(hx));
    __half ly = __float2half_rn(y - __half2float(hy));
    __half2 h = __halves2half2(hx, hy);
    __half2 l = __halves2half2(lx, ly);
    hi = *(uint32_t*)&h;
    lo = *(uint32_t*)&l;
}

// ==================== conversion kernels ===================================
__device__ __forceinline__ void convert_w_body(const float* __restrict__ W,
                                               __half* __restrict__ Wt,
                                               int K, int N, int bx, int by) {
    __shared__ float t[32][33];
    int n0 = bx * 32, k0 = by * 32;
    int tx = threadIdx.x, ty = threadIdx.y;   // 32 x 8
#pragma unroll
    for (int i = 0; i < 32; i += 8)
        t[ty + i][tx] = W[(size_t)(k0 + ty + i) * N + n0 + tx];
    __syncthreads();
#pragma unroll
    for (int i = 0; i < 32; i += 8)
        Wt[(size_t)(n0 + ty + i) * K + k0 + tx] = __float2half_rn(t[tx][ty + i]);
}

// All 4 weights in one launch: bx 0-127 Wq, 128-159 Wk, 160-191 Wv, 192-319 Wo
__global__ void convert_all(const float* __restrict__ Wq, __half* __restrict__ Wqt,
                            const float* __restrict__ Wk, __half* __restrict__ Wkt,
                            const float* __restrict__ Wv, __half* __restrict__ Wvt,
                            const float* __restrict__ Wo, __half* __restrict__ Wot) {
    const int bx = blockIdx.x;
    if (bx < 128)
        convert_w_body(Wq, Wqt, 4096, 4096, bx, blockIdx.y);
    else if (bx < 160)
        convert_w_body(Wk, Wkt, 4096, 1024, bx - 128, blockIdx.y);
    else if (bx < 192)
        convert_w_body(Wv, Wvt, 4096, 1024, bx - 160, blockIdx.y);
    else
        convert_w_body(Wo, Wot, 4096, 4096, bx - 192, blockIdx.y);
}

__global__ void split_hidden(const float* __restrict__ H, __half* __restrict__ Hh,
                             __half* __restrict__ Hl, int n) {
    int i = (blockIdx.x * blockDim.x + threadIdx.x) * 2;
    if (i >= n) return;
    float2 v = *(const float2*)(H + i);
    uint32_t h, l;
    splitA2(v.x, v.y, h, l);
    *(uint32_t*)(Hh + i) = h;
    *(uint32_t*)(Hl + i) = l;
}

// ==================== fp16 cp.async tensor-core GEMM core ==================
// R12-proven: BK=32, double-buffered cp.async, 2 CTAs/SM.
// MODE 0: store C fp32 [M][N].  MODE 1: store fp16 transposed [N][2048] (V^T).
#define KPAD 40
#define TILE_HALFS (128 * KPAD)
#define BUF3 (3 * TILE_HALFS)              // Ah, Al, B
#define GEMM_SMEM_BYTES (2 * BUF3 * 2)

template <int MODE>
__device__ __forceinline__ void gemm_core(const __half* __restrict__ Ah,
                                          const __half* __restrict__ Al,
                                          const __half* __restrict__ Bt,
                                          float* __restrict__ C,
                                          __half* __restrict__ Ct,
                                          int N, int K, int bx, int by,
                                          __half* smbuf) {
    const int tid = threadIdx.x;
    const int lane = tid & 31;
    const int w = tid >> 5;
    const int wm = w >> 1;
    const int wn = w & 1;
    const int g = lane >> 2;
    const int cc = lane & 3;
    const int quad = lane >> 3;
    const int qr = lane & 7;

    const __half* Abh = Ah + (size_t)by * 128 * K;
    const __half* Abl = Al + (size_t)by * 128 * K;
    const __half* Bb = Bt + (size_t)bx * 128 * K;

    const uint32_t smbase = smem_u32(smbuf);

    const int crow = tid >> 1;
    const int cseg = (tid & 1) * 32;

    auto issue = [&](int buf, int k0) {
        uint32_t dst = smbase + buf * BUF3 * 2 + crow * 80 + cseg;
        const char* sa = (const char*)(Abh + (size_t)crow * K + k0) + cseg;
        cp16(dst, sa);
        cp16(dst + 16, sa + 16);
        const char* sl = (const char*)(Abl + (size_t)crow * K + k0) + cseg;
        cp16(dst + TILE_HALFS * 2, sl);
        cp16(dst + TILE_HALFS * 2 + 16, sl + 16);
        const char* sb = (const char*)(Bb + (size_t)crow * K + k0) + cseg;
        cp16(dst + 2 * TILE_HALFS * 2, sb);
        cp16(dst + 2 * TILE_HALFS * 2 + 16, sb + 16);
    };

    float acc[2][8][4];
#pragma unroll
    for (int tm = 0; tm < 2; tm++)
#pragma unroll
        for (int tn = 0; tn < 8; tn++)
#pragma unroll
            for (int j = 0; j < 4; j++) acc[tm][tn][j] = 0.f;

    const uint32_t aLaneOff =
        (uint32_t)((wm * 32 + (quad & 1) * 8 + qr) * KPAD + (quad >> 1) * 8) * 2;
    const uint32_t bLaneOff =
        (uint32_t)((wn * 64 + (quad >> 1) * 8 + qr) * KPAD + (quad & 1) * 8) * 2;

    auto mma_tile = [&](int buf) {
        const uint32_t sAh = smbase + buf * BUF3 * 2;
        const uint32_t sAl = sAh + TILE_HALFS * 2;
        const uint32_t sBh = sAh + 2 * TILE_HALFS * 2;
#pragma unroll
        for (int ks = 0; ks < 32; ks += 16) {
            uint32_t ah[2][4], al[2][4];
#pragma unroll
            for (int tm = 0; tm < 2; tm++) {
                uint32_t off = aLaneOff + (uint32_t)(tm * 16 * KPAD + ks) * 2;
                ldsm_x4(ah[tm][0], ah[tm][1], ah[tm][2], ah[tm][3], sAh + off);
                ldsm_x4(al[tm][0], al[tm][1], al[tm][2], al[tm][3], sAl + off);
            }
            uint32_t bh[4][4];
#pragma unroll
            for (int tp = 0; tp < 4; tp++) {
                uint32_t off = bLaneOff + (uint32_t)(tp * 16 * KPAD + ks) * 2;
                ldsm_x4(bh[tp][0], bh[tp][1], bh[tp][2], bh[tp][3], sBh + off);
            }
#pragma unroll
            for (int tp = 0; tp < 4; tp++)
#pragma unroll
                for (int half = 0; half < 2; half++)
#pragma unroll
                    for (int tm = 0; tm < 2; tm++)
                        mma16816(acc[tm][tp * 2 + half], ah[tm], &bh[tp][half * 2]);
#pragma unroll
            for (int tp = 0; tp < 4; tp++)
#pragma unroll
                for (int half = 0; half < 2; half++)
#pragma unroll
                    for (int tm = 0; tm < 2; tm++)
                        mma16816(acc[tm][tp * 2 + half], al[tm], &bh[tp][half * 2]);
        }
    };

    const int ntiles = K / 32;

    issue(0, 0);
    CP_COMMIT;
    issue(1, 32);
    CP_COMMIT;

    for (int t = 0; t < ntiles; t++) {
        CP_WAIT1;
        __syncthreads();
        mma_tile(t & 1);
        __syncthreads();
        if (t + 2 < ntiles) issue(t & 1, (t + 2) * 32);
        CP_COMMIT;
    }

#pragma unroll
    for (int tm = 0; tm < 2; tm++) {
        int row0 = by * 128 + wm * 32 + tm * 16 + g;
#pragma unroll
        for (int tn = 0; tn < 8; tn++) {
            int col = bx * 128 + wn * 64 + tn * 8 + 2 * cc;
            if (MODE == 0) {
                *(float2*)(C + (size_t)row0 * N + col) =
                    make_float2(acc[tm][tn][0], acc[tm][tn][1]);
                *(float2*)(C + (size_t)(row0 + 8) * N + col) =
                    make_float2(acc[tm][tn][2], acc[tm][tn][3]);
            } else {
                Ct[(size_t)col * 2048 + row0] = __float2half_rn(acc[tm][tn][0]);
                Ct[(size_t)(col + 1) * 2048 + row0] = __float2half_rn(acc[tm][tn][1]);
                Ct[(size_t)col * 2048 + row0 + 8] = __float2half_rn(acc[tm][tn][2]);
                Ct[(size_t)(col + 1) * 2048 + row0 + 8] = __float2half_rn(acc[tm][tn][3]);
            }
        }
    }
}

// Merged Q + K + V projections: one 768-CTA launch, one tail.
__global__ __launch_bounds__(256, 2) void hgemm3_qkv(const __half* __restrict__ Ah,
                                                     const __half* __restrict__ Al,
                                                     const __half* __restrict__ Bq,
                                                     const __half* __restrict__ Bk,
                                                     const __half* __restrict__ Bv,
                                                     float* __restrict__ Cq,
                                                     float* __restrict__ Ck,
                                                     __half* __restrict__ Vt) {
    extern __shared__ __half smbuf[];
    const int bx = blockIdx.x;
    if (bx < 32)
        gemm_core<0>(Ah, Al, Bq, Cq, (__half*)0, 4096, 4096, bx, blockIdx.y, smbuf);
    else if (bx < 40)
        gemm_core<0>(Ah, Al, Bk, Ck, (__half*)0, 1024, 4096, bx - 32, blockIdx.y, smbuf);
    else
        gemm_core<1>(Ah, Al, Bv, (float*)0, Vt, 1024, 4096, bx - 40, blockIdx.y, smbuf);
}

// O projection
__global__ __launch_bounds__(256, 2) void hgemm3(const __half* __restrict__ Ah,
                                                 const __half* __restrict__ Al,
                                                 const __half* __restrict__ Bt,
                                                 float* __restrict__ C,
                                                 int N, int K) {
    extern __shared__ __half smbuf[];
    gemm_core<0>(Ah, Al, Bt, C, (__half*)0, N, K, blockIdx.x, blockIdx.y, smbuf);
}

// ---------------- RoPE cos/sin table (fp64 for phase accuracy) -------------
__global__ void rope_table(const int* __restrict__ positions) {
    int idx = blockIdx.x * blockDim.x + threadIdx.x;
    if (idx >= 2048 * 64) return;
    int t = idx >> 6;
    int j = idx & 63;
    double inv = exp(-(double)j * (log(1.0e6) / 64.0));
    double f = (double)positions[t] * inv;
    g_cos[idx] = (float)cos(f);
    g_sin[idx] = (float)sin(f);
}

// ---------------- fused RMSNorm + RoPE; K written directly as fp16 ---------
__global__ void rmsrope_both(float* __restrict__ Q, const float* __restrict__ Kin,
                             __half* __restrict__ Kout,
                             const float* __restrict__ qw,
                             const float* __restrict__ kw) {
    int wg = (blockIdx.x * blockDim.x + threadIdx.x) >> 5;
    int lane = threadIdx.x & 31;

    const float* x;
    int t;
    const float* w;
    bool isQ;
    float* xq = 0;
    __half* xk = 0;
    if (wg < 2048 * 32) {
        t = wg >> 5;
        int h = wg & 31;
        xq = Q + (size_t)t * 4096 + h * 128;
        x = xq;
        w = qw;
        isQ = true;
    } else {
        int wg2 = wg - 2048 * 32;
        if (wg2 >= 2048 * 8) return;
        t = wg2 >> 3;
        int h = wg2 & 7;
        x = Kin + (size_t)t * 1024 + h * 128;
        xk = Kout + (size_t)t * 1024 + h * 128;
        w = kw;
        isQ = false;
    }

    float v0 = x[lane], v1 = x[lane + 32], v2 = x[lane + 64], v3 = x[lane + 96];
    float ss = v0 * v0 + v1 * v1 + v2 * v2 + v3 * v3;
#pragma unroll
    for (int off = 16; off > 0; off >>= 1) ss += __shfl_xor_sync(0xffffffffu, ss, off);
    float rms = rsqrtf(ss * (1.f / 128.f) + 1e-6f);

    v0 *= rms * w[lane];
    v1 *= rms * w[lane + 32];
    v2 *= rms * w[lane + 64];
    v3 *= rms * w[lane + 96];

    float c0 = g_cos[t * 64 + lane],      s0 = g_sin[t * 64 + lane];
    float c1 = g_cos[t * 64 + lane + 32], s1 = g_sin[t * 64 + lane + 32];

    float r0 = v0 * c0 - v2 * s0;
    float r2 = v2 * c0 + v0 * s0;
    float r1 = v1 * c1 - v3 * s1;
    float r3 = v3 * c1 + v1 * s1;

    if (isQ) {
        xq[lane] = r0;
        xq[lane + 64] = r2;
        xq[lane + 32] = r1;
        xq[lane + 96] = r3;
    } else {
        xk[lane] = __float2half_rn(r0);
        xk[lane + 64] = __float2half_rn(r2);
        xk[lane + 32] = __float2half_rn(r1);
        xk[lane + 96] = __float2half_rn(r3);
    }
}

// ==================== tensor-core causal flash attention ===================
// Single-buffered K/V (smem 103 KB) -> 2 CTAs/SM; inter-CTA overlap hides
// the intra-CTA load exposure. Math identical to R14.
#define DPAD 136
#define VPAD 72
#define AQ_HALFS (128 * DPAD)
#define KBUF_HALFS (64 * DPAD)
#define VBUF_HALFS (128 * VPAD)
#define ATTN_SMEM_BYTES ((2 * AQ_HALFS + KBUF_HALFS + VBUF_HALFS) * 2)

__global__ __launch_bounds__(256, 2) void attn_mma(const float* __restrict__ Q,
                                                   const __half* __restrict__ Kg,
                                                   const __half* __restrict__ Vtg,
                                                   __half* __restrict__ Oh,
                                                   __half* __restrict__ Ol) {
    extern __shared__ __half asm_buf[];
    __half* Qh = asm_buf;
    __half* Ql = Qh + AQ_HALFS;
    __half* Kb = Ql + AQ_HALFS;                // 1 buffer
    __half* Vb = Kb + KBUF_HALFS;              // 1 buffer

    const uint32_t sQh = smem_u32(Qh);
    const uint32_t sQl = smem_u32(Ql);
    const uint32_t sKh = smem_u32(Kb);
    const uint32_t sVh = smem_u32(Vb);

    const int qbi = 15 - blockIdx.x;
    const int h = blockIdx.y;
    const int kvh = h >> 2;
    const int tid = threadIdx.x;
    const int lane = tid & 31;
    const int w = tid >> 5;
    const int g = lane >> 2;
    const int cc = lane & 3;
    const int quad = lane >> 3;
    const int qr = lane & 7;

    const int ntiles = 2 * (qbi + 1);
    const float scale = 0.08838834764831845f;

    // cp.async mapping for K / Vt tiles
    const int krow = tid >> 2;
    const int kc0 = (tid & 3) * 16;
    const int vrow = tid >> 1;
    const int vc0 = (tid & 1) * 16;

    auto issue_kv = [&](int kb) {
        const char* ks = (const char*)(Kg + (size_t)(kb * 64 + krow) * 1024 + kvh * 128);
        uint32_t kd = sKh + krow * (DPAD * 2);
#pragma unroll
        for (int i = 0; i < 4; i++)
            cp16(kd + kc0 + i * 64, ks + kc0 + i * 64);
        const char* vs = (const char*)(Vtg + (size_t)(kvh * 128 + vrow) * 2048 + kb * 64);
        uint32_t vd = sVh + vrow * (VPAD * 2);
#pragma unroll
        for (int i = 0; i < 4; i++)
            cp16(vd + vc0 + i * 32, vs + vc0 + i * 32);
    };

    // prologue: kick off KV tile 0, then stage Q (split hi/lo)
    issue_kv(0);
    CP_COMMIT;
    {
        const int row = tid >> 1;
        const int half = tid & 1;
        const float* qp = Q + (size_t)(qbi * 128 + row) * 4096 + h * 128 + half * 64;
#pragma unroll
        for (int i = 0; i < 32; i++) {
            float2 v = *(const float2*)(qp + 2 * i);
            uint32_t hh, ll;
            splitA2(v.x, v.y, hh, ll);
            int off = row * DPAD + half * 64 + 2 * i;
            *(uint32_t*)&Qh[off] = hh;
            *(uint32_t*)&Ql[off] = ll;
        }
    }
    CP_WAIT0;
    __syncthreads();

    const uint32_t aQOff =
        (uint32_t)((w * 16 + (quad & 1) * 8 + qr) * DPAD + (quad >> 1) * 8) * 2;
    const uint32_t bKOff =
        (uint32_t)(((quad >> 1) * 8 + qr) * DPAD + (quad & 1) * 8) * 2;
    const uint32_t bVOff =
        (uint32_t)(((quad >> 1) * 8 + qr) * VPAD + (quad & 1) * 8) * 2;

    float oacc[16][4];
#pragma unroll
    for (int tn = 0; tn < 16; tn++)
#pragma unroll
        for (int j = 0; j < 4; j++) oacc[tn][j] = 0.f;

    float mA = -1e30f, mB = -1e30f, lA = 0.f, lB = 0.f;
    const int rowA = qbi * 128 + w * 16 + g;
    const int rowB = rowA + 8;

    for (int kb = 0; kb < ntiles; kb++) {
        // ---- S = Q K^T, 2-pass ----
        float sacc[8][4];
#pragma unroll
        for (int tn = 0; tn < 8; tn++)
#pragma unroll
            for (int j = 0; j < 4; j++) sacc[tn][j] = 0.f;

#pragma unroll
        for (int ks = 0; ks < 128; ks += 16) {
            uint32_t ah[4], al[4];
            uint32_t aoff = aQOff + (uint32_t)ks * 2;
            ldsm_x4(ah[0], ah[1], ah[2], ah[3], sQh + aoff);
            ldsm_x4(al[0], al[1], al[2], al[3], sQl + aoff);
            uint32_t bh[4][4];
#pragma unroll
            for (int p = 0; p < 4; p++) {
                uint32_t boff = bKOff + (uint32_t)(p * 16 * DPAD + ks) * 2;
                ldsm_x4(bh[p][0], bh[p][1], bh[p][2], bh[p][3], sKh + boff);
            }
#pragma unroll
            for (int p = 0; p < 4; p++)
#pragma unroll
                for (int half = 0; half < 2; half++)
                    mma16816(sacc[2 * p + half], ah, &bh[p][half * 2]);
#pragma unroll
            for (int p = 0; p < 4; p++)
#pragma unroll
                for (int half = 0; half < 2; half++)
                    mma16816(sacc[2 * p + half], al, &bh[p][half * 2]);
        }

        // ---- softmax on fragments ----
        float mxA = -1e30f, mxB = -1e30f;
#pragma unroll
        for (int tn = 0; tn < 8; tn++) {
            int colbase = kb * 64 + tn * 8 + 2 * cc;
            float s0 = sacc[tn][0] * scale;
            float s1 = sacc[tn][1] * scale;
            float s2 = sacc[tn][2] * scale;
            float s3 = sacc[tn][3] * scale;
            if (colbase > rowA) s0 = -1e30f;
            if (colbase + 1 > rowA) s1 = -1e30f;
            if (colbase > rowB) s2 = -1e30f;
            if (colbase + 1 > rowB) s3 = -1e30f;
            sacc[tn][0] = s0; sacc[tn][1] = s1;
            sacc[tn][2] = s2; sacc[tn][3] = s3;
            mxA = fmaxf(mxA, fmaxf(s0, s1));
            mxB = fmaxf(mxB, fmaxf(s2, s3));
        }
        mxA = fmaxf(mxA, __shfl_xor_sync(0xffffffffu, mxA, 1));
        mxA = fmaxf(mxA, __shfl_xor_sync(0xffffffffu, mxA, 2));
        mxB = fmaxf(mxB, __shfl_xor_sync(0xffffffffu, mxB, 1));
        mxB = fmaxf(mxB, __shfl_xor_sync(0xffffffffu, mxB, 2));

        float mnA = fmaxf(mA, mxA);
        float mnB = fmaxf(mB, mxB);
        float corrA = __expf(mA - mnA);
        float corrB = __expf(mB - mnB);
        mA = mnA;
        mB = mnB;

        float sumA = 0.f, sumB = 0.f;
#pragma unroll
        for (int tn = 0; tn < 8; tn++) {
            float p0 = __expf(sacc[tn][0] - mnA);
            float p1 = __expf(sacc[tn][1] - mnA);
            float p2 = __expf(sacc[tn][2] - mnB);
            float p3 = __expf(sacc[tn][3] - mnB);
            sacc[tn][0] = p0; sacc[tn][1] = p1;
            sacc[tn][2] = p2; sacc[tn][3] = p3;
            sumA += p0 + p1;
            sumB += p2 + p3;
        }
        sumA += __shfl_xor_sync(0xffffffffu, sumA, 1);
        sumA += __shfl_xor_sync(0xffffffffu, sumA, 2);
        sumB += __shfl_xor_sync(0xffffffffu, sumB, 1);
        sumB += __shfl_xor_sync(0xffffffffu, sumB, 2);
        lA = lA * corrA + sumA;
        lB = lB * corrB + sumB;

#pragma unroll
        for (int tn = 0; tn < 16; tn++) {
            oacc[tn][0] *= corrA;
            oacc[tn][1] *= corrA;
            oacc[tn][2] *= corrB;
            oacc[tn][3] *= corrB;
        }

        // ---- O += P V, 2-pass (P exact, V hi only) ----
#pragma unroll
        for (int j = 0; j < 4; j++) {
            uint32_t pah[4], pal[4];
            splitA2(sacc[2 * j][0], sacc[2 * j][1], pah[0], pal[0]);
            splitA2(sacc[2 * j][2], sacc[2 * j][3], pah[1], pal[1]);
            splitA2(sacc[2 * j + 1][0], sacc[2 * j + 1][1], pah[2], pal[2]);
            splitA2(sacc[2 * j + 1][2], sacc[2 * j + 1][3], pah[3], pal[3]);
#pragma unroll
            for (int pp = 0; pp < 4; pp++) {
                uint32_t bh[2][4];
#pragma unroll
                for (int i = 0; i < 2; i++) {
                    uint32_t voff = bVOff +
                        (uint32_t)((2 * pp + i) * 16 * VPAD + j * 16) * 2;
                    ldsm_x4(bh[i][0], bh[i][1], bh[i][2], bh[i][3], sVh + voff);
                }
#pragma unroll
                for (int i = 0; i < 2; i++)
#pragma unroll
                    for (int half = 0; half < 2; half++)
                        mma16816(oacc[2 * (2 * pp + i) + half], pah, &bh[i][half * 2]);
#pragma unroll
                for (int i = 0; i < 2; i++)
#pragma unroll
                    for (int half = 0; half < 2; half++)
                        mma16816(oacc[2 * (2 * pp + i) + half], pal, &bh[i][half * 2]);
            }
        }

        // ---- single-buffer refill: everyone done reading, then reload ----
        __syncthreads();
        if (kb + 1 < ntiles) {
            issue_kv(kb + 1);
            CP_COMMIT;
            CP_WAIT0;
        }
        __syncthreads();
    }

    // ---- epilogue: write O as fp16 hi/lo split ----
    const float invA = 1.f / lA;
    const float invB = 1.f / lB;
#pragma unroll
    for (int tn = 0; tn < 16; tn++) {
        int d = tn * 8 + 2 * cc;
        uint32_t hh, ll;
        splitA2(oacc[tn][0] * invA, oacc[tn][1] * invA, hh, ll);
        *(uint32_t*)(Oh + (size_t)rowA * 4096 + h * 128 + d) = hh;
        *(uint32_t*)(Ol + (size_t)rowA * 4096 + h * 128 + d) = ll;
        splitA2(oacc[tn][2] * invB, oacc[tn][3] * invB, hh, ll);
        *(uint32_t*)(Oh + (size_t)rowB * 4096 + h * 128 + d) = hh;
        *(uint32_t*)(Ol + (size_t)rowB * 4096 + h * 128 + d) = ll;
    }
}

// ---------------- launch ----------------------------------------------------
extern "C" void kernel_launch(void* const* d_in, const int* in_sizes, int n_in,
                              void* d_out, int out_size) {
    const float* hidden    = (const float*)d_in[0];
    const int*   positions = (const int*)d_in[1];
    const float* Wq        = (const float*)d_in[2];
    const float* Wk        = (const float*)d_in[3];
    const float* Wv        = (const float*)d_in[4];
    const float* Wo        = (const float*)d_in[5];
    const float* q_norm_w  = (const float*)d_in[6];
    const float* k_norm_w  = (const float*)d_in[7];
    float* out = (float*)d_out;

    float* q;  cudaGetSymbolAddress((void**)&q, g_q);
    float* k;  cudaGetSymbolAddress((void**)&k, g_k);
    __half* wqt; cudaGetSymbolAddress((void**)&wqt, g_wqt);
    __half* wkt; cudaGetSymbolAddress((void**)&wkt, g_wkt);
    __half* wvt; cudaGetSymbolAddress((void**)&wvt, g_wvt);
    __half* wot; cudaGetSymbolAddress((void**)&wot, g_wot);
    __half* hh;  cudaGetSymbolAddress((void**)&hh, g_hh);
    __half* hl;  cudaGetSymbolAddress((void**)&hl, g_hl);
    __half* oh;  cudaGetSymbolAddress((void**)&oh, g_oh);
    __half* ol;  cudaGetSymbolAddress((void**)&ol, g_ol);
    __half* kh;  cudaGetSymbolAddress((void**)&kh, g_kh);
    __half* vt;  cudaGetSymbolAddress((void**)&vt, g_vt);

    cudaFuncSetAttribute(hgemm3, cudaFuncAttributeMaxDynamicSharedMemorySize,
                         GEMM_SMEM_BYTES);
    cudaFuncSetAttribute(hgemm3_qkv, cudaFuncAttributeMaxDynamicSharedMemorySize,
                         GEMM_SMEM_BYTES);
    cudaFuncSetAttribute(attn_mma, cudaFuncAttributeMaxDynamicSharedMemorySize,
                         ATTN_SMEM_BYTES);

    // 1: split hidden into fp16 hi/lo
    split_hidden<<<(2048 * 4096 / 2 + 255) / 256, 256>>>(hidden, hh, hl,
                                                         2048 * 4096);
    // 2: all 4 weights -> fp16 [N][K] in one launch
    convert_all<<<dim3(320, 128), dim3(32, 8)>>>(Wq, wqt, Wk, wkt,
                                                 Wv, wvt, Wo, wot);
    // 3: rope table
    rope_table<<<(2048 * 64 + 255) / 256, 256>>>(positions);
    // 4: merged Q + K + V projections (ncu capture slot)
    hgemm3_qkv<<<dim3(48, 16), 256, GEMM_SMEM_BYTES>>>(hh, hl, wqt, wkt, wvt,
                                                       q, k, vt);
    // 5: fused rmsnorm+rope (K emitted fp16)
    rmsrope_both<<<(2048 * 40) / 8, 256>>>(q, k, kh, q_norm_w, k_norm_w);
    // 6: attention (2 CTAs/SM)
    attn_mma<<<dim3(16, 32), 256, ATTN_SMEM_BYTES>>>(q, kh, vt, oh, ol);
    // 7: output projection
    hgemm3<<<dim3(32, 16), 256, GEMM_SMEM_BYTES>>>(oh, ol, wot, out, 4096, 4096);
}

// round 16
// speedup vs baseline: 1.0388x; 1.0388x over previous
#include <cuda_runtime.h>
#include <cuda_fp16.h>
#include <math.h>
#include <stdint.h>

// ---------------- scratch (device globals: no allocation allowed) ----------
__device__ float g_q[2048 * 4096];
__device__ float g_k[2048 * 1024];
__device__ float g_cos[2048 * 64];
__device__ float g_sin[2048 * 64];
__device__ __half g_wqt[4096 * 4096];   // Wq^T [N][K]
__device__ __half g_wkt[1024 * 4096];
__device__ __half g_wvt[1024 * 4096];
__device__ __half g_wot[4096 * 4096];   // Wo^T
__device__ __half g_hh[2048 * 4096];    // hidden hi
__device__ __half g_hl[2048 * 4096];    // hidden lo
__device__ __half g_oh[2048 * 4096];    // attn out hi
__device__ __half g_ol[2048 * 4096];    // attn out lo
__device__ __half g_kh[2048 * 1024];    // K after rmsnorm+rope, fp16
__device__ __half g_vt[1024 * 2048];    // V transposed [ch][tok] fp16

// ==================== shared helpers =======================================
__device__ __forceinline__ void mma16816(float acc[4], const uint32_t a[4],
                                         const uint32_t b[2]) {
    asm("mma.sync.aligned.m16n8k16.row.col.f32.f16.f16.f32 "
        "{%0,%1,%2,%3}, {%4,%5,%6,%7}, {%8,%9}, {%0,%1,%2,%3};\n"
        : "+f"(acc[0]), "+f"(acc[1]), "+f"(acc[2]), "+f"(acc[3])
        : "r"(a[0]), "r"(a[1]), "r"(a[2]), "r"(a[3]), "r"(b[0]), "r"(b[1]));
}

__device__ __forceinline__ void ldsm_x4(uint32_t& r0, uint32_t& r1,
                                        uint32_t& r2, uint32_t& r3,
                                        uint32_t addr) {
    asm volatile(
        "ldmatrix.sync.aligned.m8n8.x4.shared.b16 {%0,%1,%2,%3}, [%4];"
        : "=r"(r0), "=r"(r1), "=r"(r2), "=r"(r3) : "r"(addr));
}

__device__ __forceinline__ uint32_t smem_u32(const void* p) {
    uint32_t a;
    asm("{ .reg .u64 t; cvta.to.shared.u64 t, %1; cvt.u32.u64 %0, t; }"
        : "=r"(a) : "l"(p));
    return a;
}

__device__ __forceinline__ void cp16(uint32_t smem, const void* g) {
    asm volatile("cp.async.cg.shared.global [%0], [%1], 16;\n"
                 :: "r"(smem), "l"(g) : "memory");
}
#define CP_COMMIT asm volatile("cp.async.commit_group;\n" ::: "memory")
#define CP_WAIT1 asm volatile("cp.async.wait_group 1;\n" ::: "memory")

// fp16 exact split: x = hi + lo (~24 bits)
__device__ __forceinline__ void splitA2(float x, float y, uint32_t& hi, uint32_t& lo) {
    __half hx = __float2half_rn(x);
    __half hy = __float2half_rn(y);
    __half lx = __float2half_rn(x - __half2float(hx));
    __half ly = __float2half_rn(y - __half2float(hy));
    __half2 h = __halves2half2(hx, hy);
    __half2 l = __halves2half2(lx, ly);
    hi = *(uint32_t*)&h;
    lo = *(uint32_t*)&l;
}

// ==================== conversion kernels ===================================
__device__ __forceinline__ void convert_w_body(const float* __restrict__ W,
                                               __half* __restrict__ Wt,
                                               int K, int N, int bx, int by) {
    __shared__ float t[32][33];
    int n0 = bx * 32, k0 = by * 32;
    int tx = threadIdx.x, ty = threadIdx.y;   // 32 x 8
#pragma unroll
    for (int i = 0; i < 32; i += 8)
        t[ty + i][tx] = W[(size_t)(k0 + ty + i) * N + n0 + tx];
    __syncthreads();
#pragma unroll
    for (int i = 0; i < 32; i += 8)
        Wt[(size_t)(n0 + ty + i) * K + k0 + tx] = __float2half_rn(t[tx][ty + i]);
}

// All 4 weights + rope table in one launch.
// bx 0-127 Wq, 128-159 Wk, 160-191 Wv, 192-319 Wo, 320-323 rope (4x128 blocks)
__global__ void convert_all(const float* __restrict__ Wq, __half* __restrict__ Wqt,
                            const float* __restrict__ Wk, __half* __restrict__ Wkt,
                            const float* __restrict__ Wv, __half* __restrict__ Wvt,
                            const float* __restrict__ Wo, __half* __restrict__ Wot,
                            const int* __restrict__ positions) {
    const int bx = blockIdx.x;
    if (bx < 128) {
        convert_w_body(Wq, Wqt, 4096, 4096, bx, blockIdx.y);
    } else if (bx < 160) {
        convert_w_body(Wk, Wkt, 4096, 1024, bx - 128, blockIdx.y);
    } else if (bx < 192) {
        convert_w_body(Wv, Wvt, 4096, 1024, bx - 160, blockIdx.y);
    } else if (bx < 320) {
        convert_w_body(Wo, Wot, 4096, 4096, bx - 192, blockIdx.y);
    } else {
        // rope table block: rb in [0,512), idx covers 2048*64 entries
        int rb = (bx - 320) * 128 + blockIdx.y;
        int tid = threadIdx.y * 32 + threadIdx.x;
        int idx = rb * 256 + tid;
        if (idx < 2048 * 64) {
            int t = idx >> 6;
            int j = idx & 63;
            double inv = exp(-(double)j * (log(1.0e6) / 64.0));
            double f = (double)positions[t] * inv;
            g_cos[idx] = (float)cos(f);
            g_sin[idx] = (float)sin(f);
        }
    }
}

__global__ void split_hidden(const float* __restrict__ H, __half* __restrict__ Hh,
                             __half* __restrict__ Hl, int n) {
    int i = (blockIdx.x * blockDim.x + threadIdx.x) * 2;
    if (i >= n) return;
    float2 v = *(const float2*)(H + i);
    uint32_t h, l;
    splitA2(v.x, v.y, h, l);
    *(uint32_t*)(Hh + i) = h;
    *(uint32_t*)(Hl + i) = l;
}

// ==================== fp16 cp.async tensor-core GEMM core ==================
// R12-proven: BK=32, double-buffered cp.async, 2 CTAs/SM.
// MODE 0: store C fp32 [M][N].  MODE 1: store fp16 transposed [N][2048] (V^T).
#define KPAD 40
#define TILE_HALFS (128 * KPAD)
#define BUF3 (3 * TILE_HALFS)              // Ah, Al, B
#define GEMM_SMEM_BYTES (2 * BUF3 * 2)

template <int MODE>
__device__ __forceinline__ void gemm_core(const __half* __restrict__ Ah,
                                          const __half* __restrict__ Al,
                                          const __half* __restrict__ Bt,
                                          float* __restrict__ C,
                                          __half* __restrict__ Ct,
                                          int N, int K, int bx, int by,
                                          __half* smbuf) {
    const int tid = threadIdx.x;
    const int lane = tid & 31;
    const int w = tid >> 5;
    const int wm = w >> 1;
    const int wn = w & 1;
    const int g = lane >> 2;
    const int cc = lane & 3;
    const int quad = lane >> 3;
    const int qr = lane & 7;

    const __half* Abh = Ah + (size_t)by * 128 * K;
    const __half* Abl = Al + (size_t)by * 128 * K;
    const __half* Bb = Bt + (size_t)bx * 128 * K;

    const uint32_t smbase = smem_u32(smbuf);

    const int crow = tid >> 1;
    const int cseg = (tid & 1) * 32;

    auto issue = [&](int buf, int k0) {
        uint32_t dst = smbase + buf * BUF3 * 2 + crow * 80 + cseg;
        const char* sa = (const char*)(Abh + (size_t)crow * K + k0) + cseg;
        cp16(dst, sa);
        cp16(dst + 16, sa + 16);
        const char* sl = (const char*)(Abl + (size_t)crow * K + k0) + cseg;
        cp16(dst + TILE_HALFS * 2, sl);
        cp16(dst + TILE_HALFS * 2 + 16, sl + 16);
        const char* sb = (const char*)(Bb + (size_t)crow * K + k0) + cseg;
        cp16(dst + 2 * TILE_HALFS * 2, sb);
        cp16(dst + 2 * TILE_HALFS * 2 + 16, sb + 16);
    };

    float acc[2][8][4];
#pragma unroll
    for (int tm = 0; tm < 2; tm++)
#pragma unroll
        for (int tn = 0; tn < 8; tn++)
#pragma unroll
            for (int j = 0; j < 4; j++) acc[tm][tn][j] = 0.f;

    const uint32_t aLaneOff =
        (uint32_t)((wm * 32 + (quad & 1) * 8 + qr) * KPAD + (quad >> 1) * 8) * 2;
    const uint32_t bLaneOff =
        (uint32_t)((wn * 64 + (quad >> 1) * 8 + qr) * KPAD + (quad & 1) * 8) * 2;

    auto mma_tile = [&](int buf) {
        const uint32_t sAh = smbase + buf * BUF3 * 2;
        const uint32_t sAl = sAh + TILE_HALFS * 2;
        const uint32_t sBh = sAh + 2 * TILE_HALFS * 2;
#pragma unroll
        for (int ks = 0; ks < 32; ks += 16) {
            uint32_t ah[2][4], al[2][4];
#pragma unroll
            for (int tm = 0; tm < 2; tm++) {
                uint32_t off = aLaneOff + (uint32_t)(tm * 16 * KPAD + ks) * 2;
                ldsm_x4(ah[tm][0], ah[tm][1], ah[tm][2], ah[tm][3], sAh + off);
                ldsm_x4(al[tm][0], al[tm][1], al[tm][2], al[tm][3], sAl + off);
            }
            uint32_t bh[4][4];
#pragma unroll
            for (int tp = 0; tp < 4; tp++) {
                uint32_t off = bLaneOff + (uint32_t)(tp * 16 * KPAD + ks) * 2;
                ldsm_x4(bh[tp][0], bh[tp][1], bh[tp][2], bh[tp][3], sBh + off);
            }
#pragma unroll
            for (int tp = 0; tp < 4; tp++)
#pragma unroll
                for (int half = 0; half < 2; half++)
#pragma unroll
                    for (int tm = 0; tm < 2; tm++)
                        mma16816(acc[tm][tp * 2 + half], ah[tm], &bh[tp][half * 2]);
#pragma unroll
            for (int tp = 0; tp < 4; tp++)
#pragma unroll
                for (int half = 0; half < 2; half++)
#pragma unroll
                    for (int tm = 0; tm < 2; tm++)
                        mma16816(acc[tm][tp * 2 + half], al[tm], &bh[tp][half * 2]);
        }
    };

    const int ntiles = K / 32;

    issue(0, 0);
    CP_COMMIT;
    issue(1, 32);
    CP_COMMIT;

    for (int t = 0; t < ntiles; t++) {
        CP_WAIT1;
        __syncthreads();
        mma_tile(t & 1);
        __syncthreads();
        if (t + 2 < ntiles) issue(t & 1, (t + 2) * 32);
        CP_COMMIT;
    }

#pragma unroll
    for (int tm = 0; tm < 2; tm++) {
        int row0 = by * 128 + wm * 32 + tm * 16 + g;
#pragma unroll
        for (int tn = 0; tn < 8; tn++) {
            int col = bx * 128 + wn * 64 + tn * 8 + 2 * cc;
            if (MODE == 0) {
                *(float2*)(C + (size_t)row0 * N + col) =
                    make_float2(acc[tm][tn][0], acc[tm][tn][1]);
                *(float2*)(C + (size_t)(row0 + 8) * N + col) =
                    make_float2(acc[tm][tn][2], acc[tm][tn][3]);
            } else {
                Ct[(size_t)col * 2048 + row0] = __float2half_rn(acc[tm][tn][0]);
                Ct[(size_t)(col + 1) * 2048 + row0] = __float2half_rn(acc[tm][tn][1]);
                Ct[(size_t)col * 2048 + row0 + 8] = __float2half_rn(acc[tm][tn][2]);
                Ct[(size_t)(col + 1) * 2048 + row0 + 8] = __float2half_rn(acc[tm][tn][3]);
            }
        }
    }
}

// Merged Q + K + V projections: one 768-CTA launch, one tail.
__global__ __launch_bounds__(256, 2) void hgemm3_qkv(const __half* __restrict__ Ah,
                                                     const __half* __restrict__ Al,
                                                     const __half* __restrict__ Bq,
                                                     const __half* __restrict__ Bk,
                                                     const __half* __restrict__ Bv,
                                                     float* __restrict__ Cq,
                                                     float* __restrict__ Ck,
                                                     __half* __restrict__ Vt) {
    extern __shared__ __half smbuf[];
    const int bx = blockIdx.x;
    if (bx < 32)
        gemm_core<0>(Ah, Al, Bq, Cq, (__half*)0, 4096, 4096, bx, blockIdx.y, smbuf);
    else if (bx < 40)
        gemm_core<0>(Ah, Al, Bk, Ck, (__half*)0, 1024, 4096, bx - 32, blockIdx.y, smbuf);
    else
        gemm_core<1>(Ah, Al, Bv, (float*)0, Vt, 1024, 4096, bx - 40, blockIdx.y, smbuf);
}

// O projection
__global__ __launch_bounds__(256, 2) void hgemm3(const __half* __restrict__ Ah,
                                                 const __half* __restrict__ Al,
                                                 const __half* __restrict__ Bt,
                                                 float* __restrict__ C,
                                                 int N, int K) {
    extern __shared__ __half smbuf[];
    gemm_core<0>(Ah, Al, Bt, C, (__half*)0, N, K, blockIdx.x, blockIdx.y, smbuf);
}

// ---------------- fused RMSNorm + RoPE; K written directly as fp16 ---------
__global__ void rmsrope_both(float* __restrict__ Q, const float* __restrict__ Kin,
                             __half* __restrict__ Kout,
                             const float* __restrict__ qw,
                             const float* __restrict__ kw) {
    int wg = (blockIdx.x * blockDim.x + threadIdx.x) >> 5;
    int lane = threadIdx.x & 31;

    const float* x;
    int t;
    const float* w;
    bool isQ;
    float* xq = 0;
    __half* xk = 0;
    if (wg < 2048 * 32) {
        t = wg >> 5;
        int h = wg & 31;
        xq = Q + (size_t)t * 4096 + h * 128;
        x = xq;
        w = qw;
        isQ = true;
    } else {
        int wg2 = wg - 2048 * 32;
        if (wg2 >= 2048 * 8) return;
        t = wg2 >> 3;
        int h = wg2 & 7;
        x = Kin + (size_t)t * 1024 + h * 128;
        xk = Kout + (size_t)t * 1024 + h * 128;
        w = kw;
        isQ = false;
    }

    float v0 = x[lane], v1 = x[lane + 32], v2 = x[lane + 64], v3 = x[lane + 96];
    float ss = v0 * v0 + v1 * v1 + v2 * v2 + v3 * v3;
#pragma unroll
    for (int off = 16; off > 0; off >>= 1) ss += __shfl_xor_sync(0xffffffffu, ss, off);
    float rms = rsqrtf(ss * (1.f / 128.f) + 1e-6f);

    v0 *= rms * w[lane];
    v1 *= rms * w[lane + 32];
    v2 *= rms * w[lane + 64];
    v3 *= rms * w[lane + 96];

    float c0 = g_cos[t * 64 + lane],      s0 = g_sin[t * 64 + lane];
    float c1 = g_cos[t * 64 + lane + 32], s1 = g_sin[t * 64 + lane + 32];

    float r0 = v0 * c0 - v2 * s0;
    float r2 = v2 * c0 + v0 * s0;
    float r1 = v1 * c1 - v3 * s1;
    float r3 = v3 * c1 + v1 * s1;

    if (isQ) {
        xq[lane] = r0;
        xq[lane + 64] = r2;
        xq[lane + 32] = r1;
        xq[lane + 96] = r3;
    } else {
        xk[lane] = __float2half_rn(r0);
        xk[lane + 64] = __float2half_rn(r2);
        xk[lane + 32] = __float2half_rn(r1);
        xk[lane + 96] = __float2half_rn(r3);
    }
}

// ==================== tensor-core causal flash attention ===================
// R14-proven: Q fp32 in (split hi/lo in smem); K, V^T fp16 in gmem,
// double-buffered cp.async, 1 CTA/SM. O emitted hi/lo fp16.
#define DPAD 136
#define VPAD 72
#define AQ_HALFS (128 * DPAD)
#define KBUF_HALFS (64 * DPAD)
#define VBUF_HALFS (128 * VPAD)
#define ATTN_SMEM_BYTES ((2 * AQ_HALFS + 2 * KBUF_HALFS + 2 * VBUF_HALFS) * 2)

__global__ __launch_bounds__(256) void attn_mma(const float* __restrict__ Q,
                                                const __half* __restrict__ Kg,
                                                const __half* __restrict__ Vtg,
                                                __half* __restrict__ Oh,
                                                __half* __restrict__ Ol) {
    extern __shared__ __half asm_buf[];
    __half* Qh = asm_buf;
    __half* Ql = Qh + AQ_HALFS;
    __half* Kb = Ql + AQ_HALFS;
    __half* Vb = Kb + 2 * KBUF_HALFS;

    const uint32_t sQh = smem_u32(Qh);
    const uint32_t sQl = smem_u32(Ql);
    const uint32_t sK0 = smem_u32(Kb);
    const uint32_t sV0 = smem_u32(Vb);

    const int qbi = 15 - blockIdx.x;
    const int h = blockIdx.y;
    const int kvh = h >> 2;
    const int tid = threadIdx.x;
    const int lane = tid & 31;
    const int w = tid >> 5;
    const int g = lane >> 2;
    const int cc = lane & 3;
    const int quad = lane >> 3;
    const int qr = lane & 7;

    const int ntiles = 2 * (qbi + 1);
    const float scale = 0.08838834764831845f;

    {
        const int row = tid >> 1;
        const int half = tid & 1;
        const float* qp = Q + (size_t)(qbi * 128 + row) * 4096 + h * 128 + half * 64;
#pragma unroll
        for (int i = 0; i < 32; i++) {
            float2 v = *(const float2*)(qp + 2 * i);
            uint32_t hh, ll;
            splitA2(v.x, v.y, hh, ll);
            int off = row * DPAD + half * 64 + 2 * i;
            *(uint32_t*)&Qh[off] = hh;
            *(uint32_t*)&Ql[off] = ll;
        }
    }

    const int krow = tid >> 2;
    const int kc0 = (tid & 3) * 16;
    const int vrow = tid >> 1;
    const int vc0 = (tid & 1) * 16;

    auto issue_kv = [&](int kb, int buf) {
        const char* ks = (const char*)(Kg + (size_t)(kb * 64 + krow) * 1024 + kvh * 128);
        uint32_t kd = sK0 + buf * KBUF_HALFS * 2 + krow * (DPAD * 2);
#pragma unroll
        for (int i = 0; i < 4; i++)
            cp16(kd + kc0 + i * 64, ks + kc0 + i * 64);
        const char* vs = (const char*)(Vtg + (size_t)(kvh * 128 + vrow) * 2048 + kb * 64);
        uint32_t vd = sV0 + buf * VBUF_HALFS * 2 + vrow * (VPAD * 2);
#pragma unroll
        for (int i = 0; i < 4; i++)
            cp16(vd + vc0 + i * 32, vs + vc0 + i * 32);
    };

    const uint32_t aQOff =
        (uint32_t)((w * 16 + (quad & 1) * 8 + qr) * DPAD + (quad >> 1) * 8) * 2;
    const uint32_t bKOff =
        (uint32_t)(((quad >> 1) * 8 + qr) * DPAD + (quad & 1) * 8) * 2;
    const uint32_t bVOff =
        (uint32_t)(((quad >> 1) * 8 + qr) * VPAD + (quad & 1) * 8) * 2;

    float oacc[16][4];
#pragma unroll
    for (int tn = 0; tn < 16; tn++)
#pragma unroll
        for (int j = 0; j < 4; j++) oacc[tn][j] = 0.f;

    float mA = -1e30f, mB = -1e30f, lA = 0.f, lB = 0.f;
    const int rowA = qbi * 128 + w * 16 + g;
    const int rowB = rowA + 8;

    issue_kv(0, 0);
    CP_COMMIT;
    __syncthreads();

    for (int kb = 0; kb < ntiles; kb++) {
        if (kb + 1 < ntiles) issue_kv(kb + 1, (kb + 1) & 1);
        CP_COMMIT;
        CP_WAIT1;
        __syncthreads();

        const uint32_t sKh = sK0 + (kb & 1) * KBUF_HALFS * 2;
        const uint32_t sVh = sV0 + (kb & 1) * VBUF_HALFS * 2;

        float sacc[8][4];
#pragma unroll
        for (int tn = 0; tn < 8; tn++)
#pragma unroll
            for (int j = 0; j < 4; j++) sacc[tn][j] = 0.f;

#pragma unroll
        for (int ks = 0; ks < 128; ks += 16) {
            uint32_t ah[4], al[4];
            uint32_t aoff = aQOff + (uint32_t)ks * 2;
            ldsm_x4(ah[0], ah[1], ah[2], ah[3], sQh + aoff);
            ldsm_x4(al[0], al[1], al[2], al[3], sQl + aoff);
            uint32_t bh[4][4];
#pragma unroll
            for (int p = 0; p < 4; p++) {
                uint32_t boff = bKOff + (uint32_t)(p * 16 * DPAD + ks) * 2;
                ldsm_x4(bh[p][0], bh[p][1], bh[p][2], bh[p][3], sKh + boff);
            }
#pragma unroll
            for (int p = 0; p < 4; p++)
#pragma unroll
                for (int half = 0; half < 2; half++)
                    mma16816(sacc[2 * p + half], ah, &bh[p][half * 2]);
#pragma unroll
            for (int p = 0; p < 4; p++)
#pragma unroll
                for (int half = 0; half < 2; half++)
                    mma16816(sacc[2 * p + half], al, &bh[p][half * 2]);
        }

        float mxA = -1e30f, mxB = -1e30f;
#pragma unroll
        for (int tn = 0; tn < 8; tn++) {
            int colbase = kb * 64 + tn * 8 + 2 * cc;
            float s0 = sacc[tn][0] * scale;
            float s1 = sacc[tn][1] * scale;
            float s2 = sacc[tn][2] * scale;
            float s3 = sacc[tn][3] * scale;
            if (colbase > rowA) s0 = -1e30f;
            if (colbase + 1 > rowA) s1 = -1e30f;
            if (colbase > rowB) s2 = -1e30f;
            if (colbase + 1 > rowB) s3 = -1e30f;
            sacc[tn][0] = s0; sacc[tn][1] = s1;
            sacc[tn][2] = s2; sacc[tn][3] = s3;
            mxA = fmaxf(mxA, fmaxf(s0, s1));
            mxB = fmaxf(mxB, fmaxf(s2, s3));
        }
        mxA = fmaxf(mxA, __shfl_xor_sync(0xffffffffu, mxA, 1));
        mxA = fmaxf(mxA, __shfl_xor_sync(0xffffffffu, mxA, 2));
        mxB = fmaxf(mxB, __shfl_xor_sync(0xffffffffu, mxB, 1));
        mxB = fmaxf(mxB, __shfl_xor_sync(0xffffffffu, mxB, 2));

        float mnA = fmaxf(mA, mxA);
        float mnB = fmaxf(mB, mxB);
        float corrA = __expf(mA - mnA);
        float corrB = __expf(mB - mnB);
        mA = mnA;
        mB = mnB;

        float sumA = 0.f, sumB = 0.f;
#pragma unroll
        for (int tn = 0; tn < 8; tn++) {
            float p0 = __expf(sacc[tn][0] - mnA);
            float p1 = __expf(sacc[tn][1] - mnA);
            float p2 = __expf(sacc[tn][2] - mnB);
            float p3 = __expf(sacc[tn][3] - mnB);
            sacc[tn][0] = p0; sacc[tn][1] = p1;
            sacc[tn][2] = p2; sacc[tn][3] = p3;
            sumA += p0 + p1;
            sumB += p2 + p3;
        }
        sumA += __shfl_xor_sync(0xffffffffu, sumA, 1);
        sumA += __shfl_xor_sync(0xffffffffu, sumA, 2);
        sumB += __shfl_xor_sync(0xffffffffu, sumB, 1);
        sumB += __shfl_xor_sync(0xffffffffu, sumB, 2);
        lA = lA * corrA + sumA;
        lB = lB * corrB + sumB;

#pragma unroll
        for (int tn = 0; tn < 16; tn++) {
            oacc[tn][0] *= corrA;
            oacc[tn][1] *= corrA;
            oacc[tn][2] *= corrB;
            oacc[tn][3] *= corrB;
        }

#pragma unroll
        for (int j = 0; j < 4; j++) {
            uint32_t pah[4], pal[4];
            splitA2(sacc[2 * j][0], sacc[2 * j][1], pah[0], pal[0]);
            splitA2(sacc[2 * j][2], sacc[2 * j][3], pah[1], pal[1]);
            splitA2(sacc[2 * j + 1][0], sacc[2 * j + 1][1], pah[2], pal[2]);
            splitA2(sacc[2 * j + 1][2], sacc[2 * j + 1][3], pah[3], pal[3]);
#pragma unroll
            for (int pp = 0; pp < 4; pp++) {
                uint32_t bh[2][4];
#pragma unroll
                for (int i = 0; i < 2; i++) {
                    uint32_t voff = bVOff +
                        (uint32_t)((2 * pp + i) * 16 * VPAD + j * 16) * 2;
                    ldsm_x4(bh[i][0], bh[i][1], bh[i][2], bh[i][3], sVh + voff);
                }
#pragma unroll
                for (int i = 0; i < 2; i++)
#pragma unroll
                    for (int half = 0; half < 2; half++)
                        mma16816(oacc[2 * (2 * pp + i) + half], pah, &bh[i][half * 2]);
#pragma unroll
                for (int i = 0; i < 2; i++)
#pragma unroll
                    for (int half = 0; half < 2; half++)
                        mma16816(oacc[2 * (2 * pp + i) + half], pal, &bh[i][half * 2]);
            }
        }
        __syncthreads();
    }

    const float invA = 1.f / lA;
    const float invB = 1.f / lB;
#pragma unroll
    for (int tn = 0; tn < 16; tn++) {
        int d = tn * 8 + 2 * cc;
        uint32_t hh, ll;
        splitA2(oacc[tn][0] * invA, oacc[tn][1] * invA, hh, ll);
        *(uint32_t*)(Oh + (size_t)rowA * 4096 + h * 128 + d) = hh;
        *(uint32_t*)(Ol + (size_t)rowA * 4096 + h * 128 + d) = ll;
        splitA2(oacc[tn][2] * invB, oacc[tn][3] * invB, hh, ll);
        *(uint32_t*)(Oh + (size_t)rowB * 4096 + h * 128 + d) = hh;
        *(uint32_t*)(Ol + (size_t)rowB * 4096 + h * 128 + d) = ll;
    }
}

// ---------------- launch ----------------------------------------------------
extern "C" void kernel_launch(void* const* d_in, const int* in_sizes, int n_in,
                              void* d_out, int out_size) {
    const float* hidden    = (const float*)d_in[0];
    const int*   positions = (const int*)d_in[1];
    const float* Wq        = (const float*)d_in[2];
    const float* Wk        = (const float*)d_in[3];
    const float* Wv        = (const float*)d_in[4];
    const float* Wo        = (const float*)d_in[5];
    const float* q_norm_w  = (const float*)d_in[6];
    const float* k_norm_w  = (const float*)d_in[7];
    float* out = (float*)d_out;

    float* q;  cudaGetSymbolAddress((void**)&q, g_q);
    float* k;  cudaGetSymbolAddress((void**)&k, g_k);
    __half* wqt; cudaGetSymbolAddress((void**)&wqt, g_wqt);
    __half* wkt; cudaGetSymbolAddress((void**)&wkt, g_wkt);
    __half* wvt; cudaGetSymbolAddress((void**)&wvt, g_wvt);
    __half* wot; cudaGetSymbolAddress((void**)&wot, g_wot);
    __half* hh;  cudaGetSymbolAddress((void**)&hh, g_hh);
    __half* hl;  cudaGetSymbolAddress((void**)&hl, g_hl);
    __half* oh;  cudaGetSymbolAddress((void**)&oh, g_oh);
    __half* ol;  cudaGetSymbolAddress((void**)&ol, g_ol);
    __half* kh;  cudaGetSymbolAddress((void**)&kh, g_kh);
    __half* vt;  cudaGetSymbolAddress((void**)&vt, g_vt);

    cudaFuncSetAttribute(hgemm3, cudaFuncAttributeMaxDynamicSharedMemorySize,
                         GEMM_SMEM_BYTES);
    cudaFuncSetAttribute(hgemm3_qkv, cudaFuncAttributeMaxDynamicSharedMemorySize,
                         GEMM_SMEM_BYTES);
    cudaFuncSetAttribute(attn_mma, cudaFuncAttributeMaxDynamicSharedMemorySize,
                         ATTN_SMEM_BYTES);

    // 1: split hidden into fp16 hi/lo
    split_hidden<<<(2048 * 4096 / 2 + 255) / 256, 256>>>(hidden, hh, hl,
                                                         2048 * 4096);
    // 2: all 4 weights -> fp16 [N][K] + rope table, one launch
    convert_all<<<dim3(324, 128), dim3(32, 8)>>>(Wq, wqt, Wk, wkt,
                                                 Wv, wvt, Wo, wot, positions);
    // 3: merged Q + K + V projections (ncu capture slot)
    hgemm3_qkv<<<dim3(48, 16), 256, GEMM_SMEM_BYTES>>>(hh, hl, wqt, wkt, wvt,
                                                       q, k, vt);
    // 4: fused rmsnorm+rope (K emitted fp16)
    rmsrope_both<<<(2048 * 40) / 8, 256>>>(q, k, kh, q_norm_w, k_norm_w);
    // 5: attention (R14 double-buffered, 1 CTA/SM)
    attn_mma<<<dim3(16, 32), 256, ATTN_SMEM_BYTES>>>(q, kh, vt, oh, ol);
    // 6: output projection
    hgemm3<<<dim3(32, 16), 256, GEMM_SMEM_BYTES>>>(oh, ol, wot, out, 4096, 4096);
}

// round 17
// speedup vs baseline: 1.0493x; 1.0101x over previous
#include <cuda_runtime.h>
#include <cuda_fp16.h>
#include <math.h>
#include <stdint.h>

// ---------------- scratch (device globals: no allocation allowed) ----------
__device__ float g_q[2048 * 4096];
__device__ float g_k[2048 * 1024];
__device__ float g_cos[2048 * 64];
__device__ float g_sin[2048 * 64];
__device__ __half g_wqt[4096 * 4096];   // Wq^T [N][K]
__device__ __half g_wkt[1024 * 4096];
__device__ __half g_wvt[1024 * 4096];
__device__ __half g_wot[4096 * 4096];   // Wo^T
__device__ __half g_hh[2048 * 4096];    // hidden hi
__device__ __half g_hl[2048 * 4096];    // hidden lo
__device__ __half g_oh[2048 * 4096];    // attn out hi
__device__ __half g_ol[2048 * 4096];    // attn out lo
__device__ __half g_kh[2048 * 1024];    // K after rmsnorm+rope, fp16
__device__ __half g_vt[1024 * 2048];    // V transposed [ch][tok] fp16
__device__ __half g_qh[2048 * 4096];    // Q after rmsnorm+rope, hi
__device__ __half g_ql[2048 * 4096];    // Q after rmsnorm+rope, lo

// ==================== shared helpers =======================================
__device__ __forceinline__ void mma16816(float acc[4], const uint32_t a[4],
                                         const uint32_t b[2]) {
    asm("mma.sync.aligned.m16n8k16.row.col.f32.f16.f16.f32 "
        "{%0,%1,%2,%3}, {%4,%5,%6,%7}, {%8,%9}, {%0,%1,%2,%3};\n"
        : "+f"(acc[0]), "+f"(acc[1]), "+f"(acc[2]), "+f"(acc[3])
        : "r"(a[0]), "r"(a[1]), "r"(a[2]), "r"(a[3]), "r"(b[0]), "r"(b[1]));
}

__device__ __forceinline__ void ldsm_x4(uint32_t& r0, uint32_t& r1,
                                        uint32_t& r2, uint32_t& r3,
                                        uint32_t addr) {
    asm volatile(
        "ldmatrix.sync.aligned.m8n8.x4.shared.b16 {%0,%1,%2,%3}, [%4];"
        : "=r"(r0), "=r"(r1), "=r"(r2), "=r"(r3) : "r"(addr));
}

__device__ __forceinline__ uint32_t smem_u32(const void* p) {
    uint32_t a;
    asm("{ .reg .u64 t; cvta.to.shared.u64 t, %1; cvt.u32.u64 %0, t; }"
        : "=r"(a) : "l"(p));
    return a;
}

__device__ __forceinline__ void cp16(uint32_t smem, const void* g) {
    asm volatile("cp.async.cg.shared.global [%0], [%1], 16;\n"
                 :: "r"(smem), "l"(g) : "memory");
}
#define CP_COMMIT asm volatile("cp.async.commit_group;\n" ::: "memory")
#define CP_WAIT1 asm volatile("cp.async.wait_group 1;\n" ::: "memory")

// fp16 exact split: x = hi + lo (~24 bits)
__device__ __forceinline__ void splitA2(float x, float y, uint32_t& hi, uint32_t& lo) {
    __half hx = __float2half_rn(x);
    __half hy = __float2half_rn(y);
    __half lx = __float2half_rn(x - __half2float(hx));
    __half ly = __float2half_rn(y - __half2float(hy));
    __half2 h = __halves2half2(hx, hy);
    __half2 l = __halves2half2(lx, ly);
    hi = *(uint32_t*)&h;
    lo = *(uint32_t*)&l;
}

// ==================== conversion kernels ===================================
__device__ __forceinline__ void convert_w_body(const float* __restrict__ W,
                                               __half* __restrict__ Wt,
                                               int K, int N, int bx, int by) {
    __shared__ float t[32][33];
    int n0 = bx * 32, k0 = by * 32;
    int tx = threadIdx.x, ty = threadIdx.y;   // 32 x 8
#pragma unroll
    for (int i = 0; i < 32; i += 8)
        t[ty + i][tx] = W[(size_t)(k0 + ty + i) * N + n0 + tx];
    __syncthreads();
#pragma unroll
    for (int i = 0; i < 32; i += 8)
        Wt[(size_t)(n0 + ty + i) * K + k0 + tx] = __float2half_rn(t[tx][ty + i]);
}

// All 4 weights + rope table + hidden split in ONE launch.
// bx 0-127 Wq, 128-159 Wk, 160-191 Wv, 192-319 Wo,
// 320-323 rope (4x128 blocks), 324-387 hidden split (64x128 blocks)
__global__ void convert_all(const float* __restrict__ Wq, __half* __restrict__ Wqt,
                            const float* __restrict__ Wk, __half* __restrict__ Wkt,
                            const float* __restrict__ Wv, __half* __restrict__ Wvt,
                            const float* __restrict__ Wo, __half* __restrict__ Wot,
                            const int* __restrict__ positions,
                            const float* __restrict__ H,
                            __half* __restrict__ Hh, __half* __restrict__ Hl) {
    const int bx = blockIdx.x;
    if (bx < 128) {
        convert_w_body(Wq, Wqt, 4096, 4096, bx, blockIdx.y);
    } else if (bx < 160) {
        convert_w_body(Wk, Wkt, 4096, 1024, bx - 128, blockIdx.y);
    } else if (bx < 192) {
        convert_w_body(Wv, Wvt, 4096, 1024, bx - 160, blockIdx.y);
    } else if (bx < 320) {
        convert_w_body(Wo, Wot, 4096, 4096, bx - 192, blockIdx.y);
    } else if (bx < 324) {
        // rope table block: rb in [0,512)
        int rb = (bx - 320) * 128 + blockIdx.y;
        int tid = threadIdx.y * 32 + threadIdx.x;
        int idx = rb * 256 + tid;
        if (idx < 2048 * 64) {
            int t = idx >> 6;
            int j = idx & 63;
            double inv = exp(-(double)j * (log(1.0e6) / 64.0));
            double f = (double)positions[t] * inv;
            g_cos[idx] = (float)cos(f);
            g_sin[idx] = (float)sin(f);
        }
    } else {
        // hidden split: sb in [0,8192), each block covers 1024 elems
        int sb = (bx - 324) * 128 + blockIdx.y;
        int tid = threadIdx.y * 32 + threadIdx.x;
        int i = sb * 1024 + tid * 4;
        float4 v = *(const float4*)(H + i);
        uint32_t h0, l0, h1, l1;
        splitA2(v.x, v.y, h0, l0);
        splitA2(v.z, v.w, h1, l1);
        *(uint2*)(Hh + i) = make_uint2(h0, h1);
        *(uint2*)(Hl + i) = make_uint2(l0, l1);
    }
}

// ==================== fp16 cp.async tensor-core GEMM core ==================
// R12-proven: BK=32, double-buffered cp.async, 2 CTAs/SM.
// MODE 0: store C fp32 [M][N].  MODE 1: store fp16 transposed [N][2048] (V^T).
#define KPAD 40
#define TILE_HALFS (128 * KPAD)
#define BUF3 (3 * TILE_HALFS)              // Ah, Al, B
#define GEMM_SMEM_BYTES (2 * BUF3 * 2)

template <int MODE>
__device__ __forceinline__ void gemm_core(const __half* __restrict__ Ah,
                                          const __half* __restrict__ Al,
                                          const __half* __restrict__ Bt,
                                          float* __restrict__ C,
                                          __half* __restrict__ Ct,
                                          int N, int K, int bx, int by,
                                          __half* smbuf) {
    const int tid = threadIdx.x;
    const int lane = tid & 31;
    const int w = tid >> 5;
    const int wm = w >> 1;
    const int wn = w & 1;
    const int g = lane >> 2;
    const int cc = lane & 3;
    const int quad = lane >> 3;
    const int qr = lane & 7;

    const __half* Abh = Ah + (size_t)by * 128 * K;
    const __half* Abl = Al + (size_t)by * 128 * K;
    const __half* Bb = Bt + (size_t)bx * 128 * K;

    const uint32_t smbase = smem_u32(smbuf);

    const int crow = tid >> 1;
    const int cseg = (tid & 1) * 32;

    auto issue = [&](int buf, int k0) {
        uint32_t dst = smbase + buf * BUF3 * 2 + crow * 80 + cseg;
        const char* sa = (const char*)(Abh + (size_t)crow * K + k0) + cseg;
        cp16(dst, sa);
        cp16(dst + 16, sa + 16);
        const char* sl = (const char*)(Abl + (size_t)crow * K + k0) + cseg;
        cp16(dst + TILE_HALFS * 2, sl);
        cp16(dst + TILE_HALFS * 2 + 16, sl + 16);
        const char* sb = (const char*)(Bb + (size_t)crow * K + k0) + cseg;
        cp16(dst + 2 * TILE_HALFS * 2, sb);
        cp16(dst + 2 * TILE_HALFS * 2 + 16, sb + 16);
    };

    float acc[2][8][4];
#pragma unroll
    for (int tm = 0; tm < 2; tm++)
#pragma unroll
        for (int tn = 0; tn < 8; tn++)
#pragma unroll
            for (int j = 0; j < 4; j++) acc[tm][tn][j] = 0.f;

    const uint32_t aLaneOff =
        (uint32_t)((wm * 32 + (quad & 1) * 8 + qr) * KPAD + (quad >> 1) * 8) * 2;
    const uint32_t bLaneOff =
        (uint32_t)((wn * 64 + (quad >> 1) * 8 + qr) * KPAD + (quad & 1) * 8) * 2;

    auto mma_tile = [&](int buf) {
        const uint32_t sAh = smbase + buf * BUF3 * 2;
        const uint32_t sAl = sAh + TILE_HALFS * 2;
        const uint32_t sBh = sAh + 2 * TILE_HALFS * 2;
#pragma unroll
        for (int ks = 0; ks < 32; ks += 16) {
            uint32_t ah[2][4], al[2][4];
#pragma unroll
            for (int tm = 0; tm < 2; tm++) {
                uint32_t off = aLaneOff + (uint32_t)(tm * 16 * KPAD + ks) * 2;
                ldsm_x4(ah[tm][0], ah[tm][1], ah[tm][2], ah[tm][3], sAh + off);
                ldsm_x4(al[tm][0], al[tm][1], al[tm][2], al[tm][3], sAl + off);
            }
            uint32_t bh[4][4];
#pragma unroll
            for (int tp = 0; tp < 4; tp++) {
                uint32_t off = bLaneOff + (uint32_t)(tp * 16 * KPAD + ks) * 2;
                ldsm_x4(bh[tp][0], bh[tp][1], bh[tp][2], bh[tp][3], sBh + off);
            }
#pragma unroll
            for (int tp = 0; tp < 4; tp++)
#pragma unroll
                for (int half = 0; half < 2; half++)
#pragma unroll
                    for (int tm = 0; tm < 2; tm++)
                        mma16816(acc[tm][tp * 2 + half], ah[tm], &bh[tp][half * 2]);
#pragma unroll
            for (int tp = 0; tp < 4; tp++)
#pragma unroll
                for (int half = 0; half < 2; half++)
#pragma unroll
                    for (int tm = 0; tm < 2; tm++)
                        mma16816(acc[tm][tp * 2 + half], al[tm], &bh[tp][half * 2]);
        }
    };

    const int ntiles = K / 32;

    issue(0, 0);
    CP_COMMIT;
    issue(1, 32);
    CP_COMMIT;

    for (int t = 0; t < ntiles; t++) {
        CP_WAIT1;
        __syncthreads();
        mma_tile(t & 1);
        __syncthreads();
        if (t + 2 < ntiles) issue(t & 1, (t + 2) * 32);
        CP_COMMIT;
    }

#pragma unroll
    for (int tm = 0; tm < 2; tm++) {
        int row0 = by * 128 + wm * 32 + tm * 16 + g;
#pragma unroll
        for (int tn = 0; tn < 8; tn++) {
            int col = bx * 128 + wn * 64 + tn * 8 + 2 * cc;
            if (MODE == 0) {
                *(float2*)(C + (size_t)row0 * N + col) =
                    make_float2(acc[tm][tn][0], acc[tm][tn][1]);
                *(float2*)(C + (size_t)(row0 + 8) * N + col) =
                    make_float2(acc[tm][tn][2], acc[tm][tn][3]);
            } else {
                Ct[(size_t)col * 2048 + row0] = __float2half_rn(acc[tm][tn][0]);
                Ct[(size_t)(col + 1) * 2048 + row0] = __float2half_rn(acc[tm][tn][1]);
                Ct[(size_t)col * 2048 + row0 + 8] = __float2half_rn(acc[tm][tn][2]);
                Ct[(size_t)(col + 1) * 2048 + row0 + 8] = __float2half_rn(acc[tm][tn][3]);
            }
        }
    }
}

// Merged Q + K + V projections: one 768-CTA launch, one tail.
__global__ __launch_bounds__(256, 2) void hgemm3_qkv(const __half* __restrict__ Ah,
                                                     const __half* __restrict__ Al,
                                                     const __half* __restrict__ Bq,
                                                     const __half* __restrict__ Bk,
                                                     const __half* __restrict__ Bv,
                                                     float* __restrict__ Cq,
                                                     float* __restrict__ Ck,
                                                     __half* __restrict__ Vt) {
    extern __shared__ __half smbuf[];
    const int bx = blockIdx.x;
    if (bx < 32)
        gemm_core<0>(Ah, Al, Bq, Cq, (__half*)0, 4096, 4096, bx, blockIdx.y, smbuf);
    else if (bx < 40)
        gemm_core<0>(Ah, Al, Bk, Ck, (__half*)0, 1024, 4096, bx - 32, blockIdx.y, smbuf);
    else
        gemm_core<1>(Ah, Al, Bv, (float*)0, Vt, 1024, 4096, bx - 40, blockIdx.y, smbuf);
}

// O projection
__global__ __launch_bounds__(256, 2) void hgemm3(const __half* __restrict__ Ah,
                                                 const __half* __restrict__ Al,
                                                 const __half* __restrict__ Bt,
                                                 float* __restrict__ C,
                                                 int N, int K) {
    extern __shared__ __half smbuf[];
    gemm_core<0>(Ah, Al, Bt, C, (__half*)0, N, K, blockIdx.x, blockIdx.y, smbuf);
}

// ---------------- fused RMSNorm + RoPE; Q -> fp16 hi/lo, K -> fp16 ---------
__global__ void rmsrope_both(const float* __restrict__ Qin,
                             __half* __restrict__ Qh, __half* __restrict__ Ql,
                             const float* __restrict__ Kin,
                             __half* __restrict__ Kout,
                             const float* __restrict__ qw,
                             const float* __restrict__ kw) {
    int wg = (blockIdx.x * blockDim.x + threadIdx.x) >> 5;
    int lane = threadIdx.x & 31;

    const float* x;
    int t;
    const float* w;
    bool isQ;
    size_t base = 0;
    if (wg < 2048 * 32) {
        t = wg >> 5;
        int h = wg & 31;
        base = (size_t)t * 4096 + h * 128;
        x = Qin + base;
        w = qw;
        isQ = true;
    } else {
        int wg2 = wg - 2048 * 32;
        if (wg2 >= 2048 * 8) return;
        t = wg2 >> 3;
        int h = wg2 & 7;
        base = (size_t)t * 1024 + h * 128;
        x = Kin + base;
        w = kw;
        isQ = false;
    }

    float v0 = x[lane], v1 = x[lane + 32], v2 = x[lane + 64], v3 = x[lane + 96];
    float ss = v0 * v0 + v1 * v1 + v2 * v2 + v3 * v3;
#pragma unroll
    for (int off = 16; off > 0; off >>= 1) ss += __shfl_xor_sync(0xffffffffu, ss, off);
    float rms = rsqrtf(ss * (1.f / 128.f) + 1e-6f);

    v0 *= rms * w[lane];
    v1 *= rms * w[lane + 32];
    v2 *= rms * w[lane + 64];
    v3 *= rms * w[lane + 96];

    float c0 = g_cos[t * 64 + lane],      s0 = g_sin[t * 64 + lane];
    float c1 = g_cos[t * 64 + lane + 32], s1 = g_sin[t * 64 + lane + 32];

    float r0 = v0 * c0 - v2 * s0;
    float r2 = v2 * c0 + v0 * s0;
    float r1 = v1 * c1 - v3 * s1;
    float r3 = v3 * c1 + v1 * s1;

    if (isQ) {
        // identical rounding to the old attention-prologue splitA2
        __half h0 = __float2half_rn(r0), h1 = __float2half_rn(r1);
        __half h2 = __float2half_rn(r2), h3 = __float2half_rn(r3);
        Qh[base + lane] = h0;
        Qh[base + lane + 32] = h1;
        Qh[base + lane + 64] = h2;
        Qh[base + lane + 96] = h3;
        Ql[base + lane] = __float2half_rn(r0 - __half2float(h0));
        Ql[base + lane + 32] = __float2half_rn(r1 - __half2float(h1));
        Ql[base + lane + 64] = __float2half_rn(r2 - __half2float(h2));
        Ql[base + lane + 96] = __float2half_rn(r3 - __half2float(h3));
    } else {
        Kout[base + lane] = __float2half_rn(r0);
        Kout[base + lane + 64] = __float2half_rn(r2);
        Kout[base + lane + 32] = __float2half_rn(r1);
        Kout[base + lane + 96] = __float2half_rn(r3);
    }
}

// ==================== tensor-core causal flash attention ===================
// R14 structure; Q now pre-split fp16 hi/lo in gmem, staged via cp.async.
#define DPAD 136
#define VPAD 72
#define AQ_HALFS (128 * DPAD)
#define KBUF_HALFS (64 * DPAD)
#define VBUF_HALFS (128 * VPAD)
#define ATTN_SMEM_BYTES ((2 * AQ_HALFS + 2 * KBUF_HALFS + 2 * VBUF_HALFS) * 2)

__global__ __launch_bounds__(256) void attn_mma(const __half* __restrict__ Qhg,
                                                const __half* __restrict__ Qlg,
                                                const __half* __restrict__ Kg,
                                                const __half* __restrict__ Vtg,
                                                __half* __restrict__ Oh,
                                                __half* __restrict__ Ol) {
    extern __shared__ __half asm_buf[];
    __half* Qh = asm_buf;
    __half* Ql = Qh + AQ_HALFS;
    __half* Kb = Ql + AQ_HALFS;
    __half* Vb = Kb + 2 * KBUF_HALFS;

    const uint32_t sQh = smem_u32(Qh);
    const uint32_t sQl = smem_u32(Ql);
    const uint32_t sK0 = smem_u32(Kb);
    const uint32_t sV0 = smem_u32(Vb);

    const int qbi = 15 - blockIdx.x;
    const int h = blockIdx.y;
    const int kvh = h >> 2;
    const int tid = threadIdx.x;
    const int lane = tid & 31;
    const int w = tid >> 5;
    const int g = lane >> 2;
    const int cc = lane & 3;
    const int quad = lane >> 3;
    const int qr = lane & 7;

    const int ntiles = 2 * (qbi + 1);
    const float scale = 0.08838834764831845f;

    // ---- Q block via cp.async (hi + lo), one commit group ----
    {
        const int row = tid >> 1;
        const int seg = (tid & 1) * 128;       // bytes within 256B row
        const char* srch =
            (const char*)(Qhg + (size_t)(qbi * 128 + row) * 4096 + h * 128) + seg;
        const char* srcl =
            (const char*)(Qlg + (size_t)(qbi * 128 + row) * 4096 + h * 128) + seg;
        uint32_t dh = sQh + row * (DPAD * 2) + seg;
        uint32_t dl = sQl + row * (DPAD * 2) + seg;
#pragma unroll
        for (int i = 0; i < 8; i++) {
            cp16(dh + i * 16, srch + i * 16);
            cp16(dl + i * 16, srcl + i * 16);
        }
    }
    CP_COMMIT;

    const int krow = tid >> 2;
    const int kc0 = (tid & 3) * 16;
    const int vrow = tid >> 1;
    const int vc0 = (tid & 1) * 16;

    auto issue_kv = [&](int kb, int buf) {
        const char* ks = (const char*)(Kg + (size_t)(kb * 64 + krow) * 1024 + kvh * 128);
        uint32_t kd = sK0 + buf * KBUF_HALFS * 2 + krow * (DPAD * 2);
#pragma unroll
        for (int i = 0; i < 4; i++)
            cp16(kd + kc0 + i * 64, ks + kc0 + i * 64);
        const char* vs = (const char*)(Vtg + (size_t)(kvh * 128 + vrow) * 2048 + kb * 64);
        uint32_t vd = sV0 + buf * VBUF_HALFS * 2 + vrow * (VPAD * 2);
#pragma unroll
        for (int i = 0; i < 4; i++)
            cp16(vd + vc0 + i * 32, vs + vc0 + i * 32);
    };

    const uint32_t aQOff =
        (uint32_t)((w * 16 + (quad & 1) * 8 + qr) * DPAD + (quad >> 1) * 8) * 2;
    const uint32_t bKOff =
        (uint32_t)(((quad >> 1) * 8 + qr) * DPAD + (quad & 1) * 8) * 2;
    const uint32_t bVOff =
        (uint32_t)(((quad >> 1) * 8 + qr) * VPAD + (quad & 1) * 8) * 2;

    float oacc[16][4];
#pragma unroll
    for (int tn = 0; tn < 16; tn++)
#pragma unroll
        for (int j = 0; j < 4; j++) oacc[tn][j] = 0.f;

    float mA = -1e30f, mB = -1e30f, lA = 0.f, lB = 0.f;
    const int rowA = qbi * 128 + w * 16 + g;
    const int rowB = rowA + 8;

    issue_kv(0, 0);
    CP_COMMIT;

    for (int kb = 0; kb < ntiles; kb++) {
        if (kb + 1 < ntiles) issue_kv(kb + 1, (kb + 1) & 1);
        CP_COMMIT;
        CP_WAIT1;          // Q + KV(kb) complete; KV(kb+1) in flight
        __syncthreads();

        const uint32_t sKh = sK0 + (kb & 1) * KBUF_HALFS * 2;
        const uint32_t sVh = sV0 + (kb & 1) * VBUF_HALFS * 2;

        float sacc[8][4];
#pragma unroll
        for (int tn = 0; tn < 8; tn++)
#pragma unroll
            for (int j = 0; j < 4; j++) sacc[tn][j] = 0.f;

#pragma unroll
        for (int ks = 0; ks < 128; ks += 16) {
            uint32_t ah[4], al[4];
            uint32_t aoff = aQOff + (uint32_t)ks * 2;
            ldsm_x4(ah[0], ah[1], ah[2], ah[3], sQh + aoff);
            ldsm_x4(al[0], al[1], al[2], al[3], sQl + aoff);
            uint32_t bh[4][4];
#pragma unroll
            for (int p = 0; p < 4; p++) {
                uint32_t boff = bKOff + (uint32_t)(p * 16 * DPAD + ks) * 2;
                ldsm_x4(bh[p][0], bh[p][1], bh[p][2], bh[p][3], sKh + boff);
            }
#pragma unroll
            for (int p = 0; p < 4; p++)
#pragma unroll
                for (int half = 0; half < 2; half++)
                    mma16816(sacc[2 * p + half], ah, &bh[p][half * 2]);
#pragma unroll
            for (int p = 0; p < 4; p++)
#pragma unroll
                for (int half = 0; half < 2; half++)
                    mma16816(sacc[2 * p + half], al, &bh[p][half * 2]);
        }

        float mxA = -1e30f, mxB = -1e30f;
#pragma unroll
        for (int tn = 0; tn < 8; tn++) {
            int colbase = kb * 64 + tn * 8 + 2 * cc;
            float s0 = sacc[tn][0] * scale;
            float s1 = sacc[tn][1] * scale;
            float s2 = sacc[tn][2] * scale;
            float s3 = sacc[tn][3] * scale;
            if (colbase > rowA) s0 = -1e30f;
            if (colbase + 1 > rowA) s1 = -1e30f;
            if (colbase > rowB) s2 = -1e30f;
            if (colbase + 1 > rowB) s3 = -1e30f;
            sacc[tn][0] = s0; sacc[tn][1] = s1;
            sacc[tn][2] = s2; sacc[tn][3] = s3;
            mxA = fmaxf(mxA, fmaxf(s0, s1));
            mxB = fmaxf(mxB, fmaxf(s2, s3));
        }
        mxA = fmaxf(mxA, __shfl_xor_sync(0xffffffffu, mxA, 1));
        mxA = fmaxf(mxA, __shfl_xor_sync(0xffffffffu, mxA, 2));
        mxB = fmaxf(mxB, __shfl_xor_sync(0xffffffffu, mxB, 1));
        mxB = fmaxf(mxB, __shfl_xor_sync(0xffffffffu, mxB, 2));

        float mnA = fmaxf(mA, mxA);
        float mnB = fmaxf(mB, mxB);
        float corrA = __expf(mA - mnA);
        float corrB = __expf(mB - mnB);
        mA = mnA;
        mB = mnB;

        float sumA = 0.f, sumB = 0.f;
#pragma unroll
        for (int tn = 0; tn < 8; tn++) {
            float p0 = __expf(sacc[tn][0] - mnA);
            float p1 = __expf(sacc[tn][1] - mnA);
            float p2 = __expf(sacc[tn][2] - mnB);
            float p3 = __expf(sacc[tn][3] - mnB);
            sacc[tn][0] = p0; sacc[tn][1] = p1;
            sacc[tn][2] = p2; sacc[tn][3] = p3;
            sumA += p0 + p1;
            sumB += p2 + p3;
        }
        sumA += __shfl_xor_sync(0xffffffffu, sumA, 1);
        sumA += __shfl_xor_sync(0xffffffffu, sumA, 2);
        sumB += __shfl_xor_sync(0xffffffffu, sumB, 1);
        sumB += __shfl_xor_sync(0xffffffffu, sumB, 2);
        lA = lA * corrA + sumA;
        lB = lB * corrB + sumB;

#pragma unroll
        for (int tn = 0; tn < 16; tn++) {
            oacc[tn][0] *= corrA;
            oacc[tn][1] *= corrA;
            oacc[tn][2] *= corrB;
            oacc[tn][3] *= corrB;
        }

#pragma unroll
        for (int j = 0; j < 4; j++) {
            uint32_t pah[4], pal[4];
            splitA2(sacc[2 * j][0], sacc[2 * j][1], pah[0], pal[0]);
            splitA2(sacc[2 * j][2], sacc[2 * j][3], pah[1], pal[1]);
            splitA2(sacc[2 * j + 1][0], sacc[2 * j + 1][1], pah[2], pal[2]);
            splitA2(sacc[2 * j + 1][2], sacc[2 * j + 1][3], pah[3], pal[3]);
#pragma unroll
            for (int pp = 0; pp < 4; pp++) {
                uint32_t bh[2][4];
#pragma unroll
                for (int i = 0; i < 2; i++) {
                    uint32_t voff = bVOff +
                        (uint32_t)((2 * pp + i) * 16 * VPAD + j * 16) * 2;
                    ldsm_x4(bh[i][0], bh[i][1], bh[i][2], bh[i][3], sVh + voff);
                }
#pragma unroll
                for (int i = 0; i < 2; i++)
#pragma unroll
                    for (int half = 0; half < 2; half++)
                        mma16816(oacc[2 * (2 * pp + i) + half], pah, &bh[i][half * 2]);
#pragma unroll
                for (int i = 0; i < 2; i++)
#pragma unroll
                    for (int half = 0; half < 2; half++)
                        mma16816(oacc[2 * (2 * pp + i) + half], pal, &bh[i][half * 2]);
            }
        }
        __syncthreads();
    }

    const float invA = 1.f / lA;
    const float invB = 1.f / lB;
#pragma unroll
    for (int tn = 0; tn < 16; tn++) {
        int d = tn * 8 + 2 * cc;
        uint32_t hh, ll;
        splitA2(oacc[tn][0] * invA, oacc[tn][1] * invA, hh, ll);
        *(uint32_t*)(Oh + (size_t)rowA * 4096 + h * 128 + d) = hh;
        *(uint32_t*)(Ol + (size_t)rowA * 4096 + h * 128 + d) = ll;
        splitA2(oacc[tn][2] * invB, oacc[tn][3] * invB, hh, ll);
        *(uint32_t*)(Oh + (size_t)rowB * 4096 + h * 128 + d) = hh;
        *(uint32_t*)(Ol + (size_t)rowB * 4096 + h * 128 + d) = ll;
    }
}

// ---------------- launch ----------------------------------------------------
extern "C" void kernel_launch(void* const* d_in, const int* in_sizes, int n_in,
                              void* d_out, int out_size) {
    const float* hidden    = (const float*)d_in[0];
    const int*   positions = (const int*)d_in[1];
    const float* Wq        = (const float*)d_in[2];
    const float* Wk        = (const float*)d_in[3];
    const float* Wv        = (const float*)d_in[4];
    const float* Wo        = (const float*)d_in[5];
    const float* q_norm_w  = (const float*)d_in[6];
    const float* k_norm_w  = (const float*)d_in[7];
    float* out = (float*)d_out;

    float* q;  cudaGetSymbolAddress((void**)&q, g_q);
    float* k;  cudaGetSymbolAddress((void**)&k, g_k);
    __half* wqt; cudaGetSymbolAddress((void**)&wqt, g_wqt);
    __half* wkt; cudaGetSymbolAddress((void**)&wkt, g_wkt);
    __half* wvt; cudaGetSymbolAddress((void**)&wvt, g_wvt);
    __half* wot; cudaGetSymbolAddress((void**)&wot, g_wot);
    __half* hh;  cudaGetSymbolAddress((void**)&hh, g_hh);
    __half* hl;  cudaGetSymbolAddress((void**)&hl, g_hl);
    __half* oh;  cudaGetSymbolAddress((void**)&oh, g_oh);
    __half* ol;  cudaGetSymbolAddress((void**)&ol, g_ol);
    __half* kh;  cudaGetSymbolAddress((void**)&kh, g_kh);
    __half* vt;  cudaGetSymbolAddress((void**)&vt, g_vt);
    __half* qh;  cudaGetSymbolAddress((void**)&qh, g_qh);
    __half* ql;  cudaGetSymbolAddress((void**)&ql, g_ql);

    cudaFuncSetAttribute(hgemm3, cudaFuncAttributeMaxDynamicSharedMemorySize,
                         GEMM_SMEM_BYTES);
    cudaFuncSetAttribute(hgemm3_qkv, cudaFuncAttributeMaxDynamicSharedMemorySize,
                         GEMM_SMEM_BYTES);
    cudaFuncSetAttribute(attn_mma, cudaFuncAttributeMaxDynamicSharedMemorySize,
                         ATTN_SMEM_BYTES);

    // 1: weights -> fp16, rope table, hidden split: ONE launch
    convert_all<<<dim3(388, 128), dim3(32, 8)>>>(Wq, wqt, Wk, wkt, Wv, wvt,
                                                 Wo, wot, positions,
                                                 hidden, hh, hl);
    // 2: merged Q + K + V projections
    hgemm3_qkv<<<dim3(48, 16), 256, GEMM_SMEM_BYTES>>>(hh, hl, wqt, wkt, wvt,
                                                       q, k, vt);
    // 3: fused rmsnorm+rope (Q emitted fp16 hi/lo, K fp16)
    rmsrope_both<<<(2048 * 40) / 8, 256>>>(q, qh, ql, k, kh, q_norm_w, k_norm_w);
    // 4: attention
    attn_mma<<<dim3(16, 32), 256, ATTN_SMEM_BYTES>>>(qh, ql, kh, vt, oh, ol);
    // 5: output projection
    hgemm3<<<dim3(32, 16), 256, GEMM_SMEM_BYTES>>>(oh, ol, wot, out, 4096, 4096);
}